// round 3
// baseline (speedup 1.0000x reference)
#include <cuda_runtime.h>
#include <math_constants.h>

// ChamferLoss via exact grid-accelerated nearest neighbor.
// d2min(p -> Q) = |p|^2 - 2 * max_j ( p.q_j - 0.5|q_j|^2 )   (same algebra as ref)
//
// 16 reference structures (uniform grids), one per (cloud, batch):
//   s in [0,8):  nonfiltered  s = which*4 + b   (which 0 = pn, 1 = gn), 8192 pts
//   s in [8,16): filtered     s = 8 + which*4+b (which 0 = pf, 1 = gf), 4096 pts
// A query point living in structure s searches partner structure s^4.
//
// Exactness: ring search terminates when best_d2 <= ((r-1)*H)^2 after
// completing all cells of Chebyshev radius <= r-1... specifically after
// completing rings 0..r, unscanned cells have Chebyshev >= r+1, so any
// unscanned point is >= r*H away (holds under coordinate clamping since
// clamping is a 1-Lipschitz projection per axis).

#define G     32
#define NCELL (G * G * G)          // 32768 cells per structure
#define H     0.32f
#define INVH  3.125f
#define RANGE 5.12f
#define NSTRUCT 16
#define CAP   8192                 // per-structure point capacity

#define NQ_TOTAL 98304             // 65536 nonfiltered + 32768 filtered

__device__ int    g_cnt  [NSTRUCT * NCELL];
__device__ int    g_start[NSTRUCT * NCELL];
__device__ int    g_cur  [NSTRUCT * NCELL];   // scatter cursor; == end after scatter
__device__ float4 g_pts  [NSTRUCT * CAP];

__device__ __forceinline__ int cell_coord(float x) {
    int c = (int)floorf((x + RANGE) * INVH);
    return min(max(c, 0), G - 1);
}

// map thread id -> (cloud base ptr, point index, structure id, direction scale)
__device__ __forceinline__ const float* map_point(
    int t, const float* pf, const float* gf, const float* pn, const float* gn,
    int* idx, int* s, float* scale)
{
    if (t < 65536) {
        const int grp = t >> 13;          // 0..7
        const int b   = grp & 3;
        *idx   = t & 8191;
        *s     = grp;
        *scale = 0.3f / (4.0f * 8192.0f);
        return ((grp < 4) ? pn : gn) + (size_t)b * 8192 * 3;
    } else {
        const int tf  = t - 65536;
        const int grp = tf >> 12;         // 0..7
        const int b   = grp & 3;
        *idx   = tf & 4095;
        *s     = 8 + grp;
        *scale = 0.7f / (4.0f * 4096.0f);
        return ((grp < 4) ? pf : gf) + (size_t)b * 4096 * 3;
    }
}

__global__ void k_zero(float* out) {
    const int i = blockIdx.x * 1024 + threadIdx.x;
    if (i < NSTRUCT * NCELL) g_cnt[i] = 0;
    if (i == 0) out[0] = 0.0f;
}

__global__ __launch_bounds__(256) void k_count(
    const float* __restrict__ pf, const float* __restrict__ gf,
    const float* __restrict__ pn, const float* __restrict__ gn)
{
    const int t = blockIdx.x * 256 + threadIdx.x;
    int i, s; float sc;
    const float* P = map_point(t, pf, gf, pn, gn, &i, &s, &sc);
    const float x = P[3 * i], y = P[3 * i + 1], z = P[3 * i + 2];
    const int cell = (cell_coord(z) * G + cell_coord(y)) * G + cell_coord(x);
    atomicAdd(&g_cnt[s * NCELL + cell], 1);
}

// one block per structure: exclusive prefix sum over its 32768 cell counts
__global__ __launch_bounds__(1024) void k_scan() {
    const int s   = blockIdx.x;
    const int tid = threadIdx.x;
    const int CPT = NCELL / 1024;        // 32 cells per thread
    const int base = s * NCELL + tid * CPT;

    int sum = 0;
    for (int k = 0; k < CPT; k++) sum += g_cnt[base + k];

    __shared__ int sh[1024];
    sh[tid] = sum;
    __syncthreads();
    #pragma unroll
    for (int off = 1; off < 1024; off <<= 1) {
        int v = (tid >= off) ? sh[tid - off] : 0;
        __syncthreads();
        sh[tid] += v;
        __syncthreads();
    }
    int run = (tid == 0) ? 0 : sh[tid - 1];  // exclusive prefix of this thread's chunk

    for (int k = 0; k < CPT; k++) {
        const int c = g_cnt[base + k];
        g_start[base + k] = run;
        g_cur[base + k]   = run;
        run += c;
    }
}

__global__ __launch_bounds__(256) void k_scatter(
    const float* __restrict__ pf, const float* __restrict__ gf,
    const float* __restrict__ pn, const float* __restrict__ gn)
{
    const int t = blockIdx.x * 256 + threadIdx.x;
    int i, s; float sc;
    const float* P = map_point(t, pf, gf, pn, gn, &i, &s, &sc);
    const float x = P[3 * i], y = P[3 * i + 1], z = P[3 * i + 2];
    const int cell = (cell_coord(z) * G + cell_coord(y)) * G + cell_coord(x);
    const int slot = atomicAdd(&g_cur[s * NCELL + cell], 1);
    const float nh = -0.5f * fmaf(x, x, fmaf(y, y, z * z));
    g_pts[s * CAP + slot] = make_float4(x, y, z, nh);
}

__global__ __launch_bounds__(256) void k_query(
    const float* __restrict__ pf, const float* __restrict__ gf,
    const float* __restrict__ pn, const float* __restrict__ gn,
    float* __restrict__ out)
{
    const int t = blockIdx.x * 256 + threadIdx.x;
    int i, s_own; float scale;
    const float* P = map_point(t, pf, gf, pn, gn, &i, &s_own, &scale);
    const int s = s_own ^ 4;             // partner structure to search

    const float px = P[3 * i], py = P[3 * i + 1], pz = P[3 * i + 2];
    const float p2 = fmaf(px, px, fmaf(py, py, pz * pz));
    const int cx = cell_coord(px), cy = cell_coord(py), cz = cell_coord(pz);

    const int*    st  = g_start + s * NCELL;
    const int*    cu  = g_cur   + s * NCELL;
    const float4* pts = g_pts   + s * CAP;

    float m = -CUDART_INF_F;             // running max of (p.q - 0.5|q|^2)

    // rings 0..1: full 3x3x3 cube, contiguous x-row ranges
    {
        const int z0 = max(cz - 1, 0), z1 = min(cz + 1, G - 1);
        const int y0 = max(cy - 1, 0), y1 = min(cy + 1, G - 1);
        const int x0 = max(cx - 1, 0), x1 = min(cx + 1, G - 1);
        for (int zz = z0; zz <= z1; zz++)
            for (int yy = y0; yy <= y1; yy++) {
                const int rb  = (zz * G + yy) * G;
                const int beg = st[rb + x0];
                const int end = cu[rb + x1];
                for (int u = beg; u < end; u++) {
                    const float4 q = pts[u];
                    m = fmaxf(m, fmaf(px, q.x, fmaf(py, q.y, fmaf(pz, q.z, q.w))));
                }
            }
    }
    float bd2 = fmaf(-2.0f, m, p2);

    // shells r = 2.. ; stop when unscanned cells provably can't beat bd2
    for (int r = 2; r < G; r++) {
        const float bound = (float)(r - 1) * H;
        if (bd2 <= bound * bound) break;
        for (int dz = -r; dz <= r; dz++) {
            const int zz = cz + dz;
            if (zz < 0 || zz >= G) continue;
            const bool zf = (dz == -r) || (dz == r);
            for (int dy = -r; dy <= r; dy++) {
                const int yy = cy + dy;
                if (yy < 0 || yy >= G) continue;
                const int rb = (zz * G + yy) * G;
                if (zf || dy == -r || dy == r) {
                    const int x0 = max(cx - r, 0), x1 = min(cx + r, G - 1);
                    const int beg = st[rb + x0], end = cu[rb + x1];
                    for (int u = beg; u < end; u++) {
                        const float4 q = pts[u];
                        m = fmaxf(m, fmaf(px, q.x, fmaf(py, q.y, fmaf(pz, q.z, q.w))));
                    }
                } else {
                    const int xl = cx - r;
                    if (xl >= 0) {
                        const int beg = st[rb + xl], end = cu[rb + xl];
                        for (int u = beg; u < end; u++) {
                            const float4 q = pts[u];
                            m = fmaxf(m, fmaf(px, q.x, fmaf(py, q.y, fmaf(pz, q.z, q.w))));
                        }
                    }
                    const int xr = cx + r;
                    if (xr < G) {
                        const int beg = st[rb + xr], end = cu[rb + xr];
                        for (int u = beg; u < end; u++) {
                            const float4 q = pts[u];
                            m = fmaxf(m, fmaf(px, q.x, fmaf(py, q.y, fmaf(pz, q.z, q.w))));
                        }
                    }
                }
            }
        }
        bd2 = fmaf(-2.0f, m, p2);
    }

    float val = bd2 * scale;

    // block reduction + single atomic
    #pragma unroll
    for (int o = 16; o; o >>= 1)
        val += __shfl_down_sync(0xffffffffu, val, o);
    __shared__ float ws[8];
    if ((threadIdx.x & 31) == 0) ws[threadIdx.x >> 5] = val;
    __syncthreads();
    if (threadIdx.x == 0) {
        float acc = 0.0f;
        #pragma unroll
        for (int w = 0; w < 8; w++) acc += ws[w];
        atomicAdd(out, acc);
    }
}

extern "C" void kernel_launch(void* const* d_in, const int* in_sizes, int n_in,
                              void* d_out, int out_size) {
    const float* pf = (const float*)d_in[0];  // pred_filtered    [4,4096,3]
    const float* gf = (const float*)d_in[1];  // gt_filtered      [4,4096,3]
    const float* pn = (const float*)d_in[2];  // pred_nonfiltered [4,8192,3]
    const float* gn = (const float*)d_in[3];  // gt_nonfiltered   [4,8192,3]
    float* out = (float*)d_out;

    k_zero<<<(NSTRUCT * NCELL + 1023) / 1024, 1024>>>(out);
    k_count<<<NQ_TOTAL / 256, 256>>>(pf, gf, pn, gn);
    k_scan<<<NSTRUCT, 1024>>>();
    k_scatter<<<NQ_TOTAL / 256, 256>>>(pf, gf, pn, gn);
    k_query<<<NQ_TOTAL / 256, 256>>>(pf, gf, pn, gn, out);
}

// round 4
// speedup vs baseline: 1.1638x; 1.1638x over previous
#include <cuda_runtime.h>
#include <math_constants.h>

// ChamferLoss via exact grid-accelerated nearest neighbor, with spatially
// coherent (cell-sorted) query order.
// d2min(p -> Q) = |p|^2 - 2 * max_j ( p.q_j - 0.5|q_j|^2 )
//
// 16 structures, one per (cloud, batch):
//   s in [0,8):  nonfiltered (0-3: pn, 4-7: gn), 8192 pts
//   s in [8,16): filtered    (8-11: pf, 12-15: gf), 4096 pts
// Structure s's points query partner structure s^4.
//
// Exactness: after completing all Chebyshev rings <= r, any unscanned point
// is >= r*H away (coordinate clamping is a 1-Lipschitz projection per axis),
// so termination when best_d2 <= ((r-1)*H)^2 is exact.

#define G     32
#define NCELL (G * G * G)
#define H     0.32f
#define INVH  3.125f
#define RANGE 5.12f
#define NSTRUCT 16
#define CAP   8192

#define NQ_TOTAL 98304

__device__ int    g_cnt  [NSTRUCT * NCELL];
__device__ int    g_start[NSTRUCT * NCELL];
__device__ int    g_cur  [NSTRUCT * NCELL];
__device__ float4 g_pts  [NSTRUCT * CAP];   // cell-sorted (x,y,z,-0.5|q|^2)

__device__ __forceinline__ int cell_coord(float x) {
    int c = (int)floorf((x + RANGE) * INVH);
    return min(max(c, 0), G - 1);
}

__device__ __forceinline__ const float* map_point(
    int t, const float* pf, const float* gf, const float* pn, const float* gn,
    int* idx, int* s)
{
    if (t < 65536) {
        const int grp = t >> 13;
        *idx = t & 8191;
        *s   = grp;
        return ((grp < 4) ? pn : gn) + (size_t)(grp & 3) * 8192 * 3;
    } else {
        const int tf  = t - 65536;
        const int grp = tf >> 12;
        *idx = tf & 4095;
        *s   = 8 + grp;
        return ((grp < 4) ? pf : gf) + (size_t)(grp & 3) * 4096 * 3;
    }
}

__global__ void k_zero(float* out) {
    const int i = blockIdx.x * 1024 + threadIdx.x;
    if (i < NSTRUCT * NCELL) g_cnt[i] = 0;
    if (i == 0) out[0] = 0.0f;
}

__global__ __launch_bounds__(256) void k_count(
    const float* __restrict__ pf, const float* __restrict__ gf,
    const float* __restrict__ pn, const float* __restrict__ gn)
{
    const int t = blockIdx.x * 256 + threadIdx.x;
    int i, s;
    const float* P = map_point(t, pf, gf, pn, gn, &i, &s);
    const float x = P[3 * i], y = P[3 * i + 1], z = P[3 * i + 2];
    const int cell = (cell_coord(z) * G + cell_coord(y)) * G + cell_coord(x);
    atomicAdd(&g_cnt[s * NCELL + cell], 1);
}

// one block per structure: exclusive prefix sum over its 32768 cell counts
__global__ __launch_bounds__(1024) void k_scan() {
    const int s   = blockIdx.x;
    const int tid = threadIdx.x;
    const int CPT = NCELL / 1024;
    const int base = s * NCELL + tid * CPT;

    int sum = 0;
    #pragma unroll
    for (int k = 0; k < CPT; k++) sum += g_cnt[base + k];

    __shared__ int sh[1024];
    sh[tid] = sum;
    __syncthreads();
    #pragma unroll
    for (int off = 1; off < 1024; off <<= 1) {
        int v = (tid >= off) ? sh[tid - off] : 0;
        __syncthreads();
        sh[tid] += v;
        __syncthreads();
    }
    int run = (tid == 0) ? 0 : sh[tid - 1];

    #pragma unroll
    for (int k = 0; k < CPT; k++) {
        const int c = g_cnt[base + k];
        g_start[base + k] = run;
        g_cur[base + k]   = run;
        run += c;
    }
}

__global__ __launch_bounds__(256) void k_scatter(
    const float* __restrict__ pf, const float* __restrict__ gf,
    const float* __restrict__ pn, const float* __restrict__ gn)
{
    const int t = blockIdx.x * 256 + threadIdx.x;
    int i, s;
    const float* P = map_point(t, pf, gf, pn, gn, &i, &s);
    const float x = P[3 * i], y = P[3 * i + 1], z = P[3 * i + 2];
    const int cell = (cell_coord(z) * G + cell_coord(y)) * G + cell_coord(x);
    const int slot = atomicAdd(&g_cur[s * NCELL + cell], 1);
    const float nh = -0.5f * fmaf(x, x, fmaf(y, y, z * z));
    g_pts[s * CAP + slot] = make_float4(x, y, z, nh);
}

// Query in CELL-SORTED order: thread t handles sorted point u of structure
// s_own. Adjacent threads share cells -> broadcast loads, coherent ring loops.
__global__ __launch_bounds__(256) void k_query(float* __restrict__ out)
{
    const int t = blockIdx.x * 256 + threadIdx.x;
    int s_own, u;
    float scale;
    if (t < 65536) {
        s_own = t >> 13;
        u     = t & 8191;
        scale = 0.3f / (4.0f * 8192.0f);
    } else {
        const int tf = t - 65536;
        s_own = 8 + (tf >> 12);
        u     = tf & 4095;
        scale = 0.7f / (4.0f * 4096.0f);
    }
    const int s = s_own ^ 4;   // partner structure

    const float4 p  = g_pts[s_own * CAP + u];
    const float px = p.x, py = p.y, pz = p.z;
    const float p2 = -2.0f * p.w;            // exact |p|^2 reconstruction
    const int cx = cell_coord(px), cy = cell_coord(py), cz = cell_coord(pz);

    const int*    st  = g_start + s * NCELL;
    const int*    cu  = g_cur   + s * NCELL;
    const float4* pts = g_pts   + s * CAP;

    float m = -CUDART_INF_F;

    // rings 0..1: full 3x3x3 cube (contiguous x-row ranges)
    {
        const int z0 = max(cz - 1, 0), z1 = min(cz + 1, G - 1);
        const int y0 = max(cy - 1, 0), y1 = min(cy + 1, G - 1);
        const int x0 = max(cx - 1, 0), x1 = min(cx + 1, G - 1);
        for (int zz = z0; zz <= z1; zz++)
            for (int yy = y0; yy <= y1; yy++) {
                const int rb  = (zz * G + yy) * G;
                const int beg = st[rb + x0];
                const int end = cu[rb + x1];
                for (int v = beg; v < end; v++) {
                    const float4 q = pts[v];
                    m = fmaxf(m, fmaf(px, q.x, fmaf(py, q.y, fmaf(pz, q.z, q.w))));
                }
            }
    }
    float bd2 = fmaf(-2.0f, m, p2);

    // shells r >= 2 until provably exact
    for (int r = 2; r < G; r++) {
        const float bound = (float)(r - 1) * H;
        if (bd2 <= bound * bound) break;
        for (int dz = -r; dz <= r; dz++) {
            const int zz = cz + dz;
            if (zz < 0 || zz >= G) continue;
            const bool zf = (dz == -r) || (dz == r);
            for (int dy = -r; dy <= r; dy++) {
                const int yy = cy + dy;
                if (yy < 0 || yy >= G) continue;
                const int rb = (zz * G + yy) * G;
                if (zf || dy == -r || dy == r) {
                    const int x0 = max(cx - r, 0), x1 = min(cx + r, G - 1);
                    const int beg = st[rb + x0], end = cu[rb + x1];
                    for (int v = beg; v < end; v++) {
                        const float4 q = pts[v];
                        m = fmaxf(m, fmaf(px, q.x, fmaf(py, q.y, fmaf(pz, q.z, q.w))));
                    }
                } else {
                    const int xl = cx - r;
                    if (xl >= 0) {
                        const int beg = st[rb + xl], end = cu[rb + xl];
                        for (int v = beg; v < end; v++) {
                            const float4 q = pts[v];
                            m = fmaxf(m, fmaf(px, q.x, fmaf(py, q.y, fmaf(pz, q.z, q.w))));
                        }
                    }
                    const int xr = cx + r;
                    if (xr < G) {
                        const int beg = st[rb + xr], end = cu[rb + xr];
                        for (int v = beg; v < end; v++) {
                            const float4 q = pts[v];
                            m = fmaxf(m, fmaf(px, q.x, fmaf(py, q.y, fmaf(pz, q.z, q.w))));
                        }
                    }
                }
            }
        }
        bd2 = fmaf(-2.0f, m, p2);
    }

    float val = bd2 * scale;

    #pragma unroll
    for (int o = 16; o; o >>= 1)
        val += __shfl_down_sync(0xffffffffu, val, o);
    __shared__ float ws[8];
    if ((threadIdx.x & 31) == 0) ws[threadIdx.x >> 5] = val;
    __syncthreads();
    if (threadIdx.x == 0) {
        float acc = 0.0f;
        #pragma unroll
        for (int w = 0; w < 8; w++) acc += ws[w];
        atomicAdd(out, acc);
    }
}

extern "C" void kernel_launch(void* const* d_in, const int* in_sizes, int n_in,
                              void* d_out, int out_size) {
    const float* pf = (const float*)d_in[0];
    const float* gf = (const float*)d_in[1];
    const float* pn = (const float*)d_in[2];
    const float* gn = (const float*)d_in[3];
    float* out = (float*)d_out;

    k_zero<<<(NSTRUCT * NCELL + 1023) / 1024, 1024>>>(out);
    k_count<<<NQ_TOTAL / 256, 256>>>(pf, gf, pn, gn);
    k_scan<<<NSTRUCT, 1024>>>();
    k_scatter<<<NQ_TOTAL / 256, 256>>>(pf, gf, pn, gn);
    k_query<<<NQ_TOTAL / 256, 256>>>(out);
}